// round 16
// baseline (speedup 1.0000x reference)
#include <cuda_runtime.h>
#include <cuda_fp16.h>
#include <math.h>
#include <stdint.h>

// ---------------------------------------------------------------------------
// Problem constants
// ---------------------------------------------------------------------------
#define B_SZ   8
#define L_SEQ  2048
#define H_DIM  1024
#define N_DIM  512
#define M_ROWS 16384            // B*L
#define K_DIM  1024             // pure fp16: K = 1024 for both GEMMs
#define N_OUT  1024

// GEMM config (converged optimum): 128x128 CTA tile, 8 warps (2m x 4n) of
// 64x32, BK=64, 3 stages, 2 CTAs/SM, register double-buffered fragments.
#define BM 128
#define BN 128
#define BK 64                   // fp16 elems per stage row (128 B data)
#define NSTAGES 3
#define KITERS (K_DIM / BK)     // 16
#define GEMM_THREADS 256

// Padded rows: 64 fp16 = 128B data + 16B pad = 144B -> conflict-free ldmatrix.
#define ROWB 144
#define TILEB (128 * ROWB)      // 18432 B per operand tile
#define STAGEB (2 * TILEB)      // 36864 B per stage
#define SMEM_DYN (NSTAGES * STAGEB)   // 110592 B -> 2 CTAs/SM

// Elementwise l-chunk size (recurrence length)
#define LCHUNK 8

// ---------------------------------------------------------------------------
// Static device buffers (allocation-free scratch)
// ---------------------------------------------------------------------------
__device__ __half g_A[(size_t)M_ROWS * K_DIM];              // 32 MB
__device__ __half g_B1[(size_t)N_OUT * K_DIM];              // 2 MB
__device__ __half g_B2[(size_t)N_OUT * K_DIM];              // 2 MB
__device__ __half g_Bu[(size_t)M_ROWS * N_OUT];             // 32 MB (Bu fp16)

// ---------------------------------------------------------------------------
// PTX helpers (sm_80-class only — legal on base compute_103 target)
// ---------------------------------------------------------------------------
__device__ __forceinline__ uint32_t smem_u32(const void* p) {
    uint32_t a;
    asm("{ .reg .u64 t; cvta.to.shared.u64 t, %1; cvt.u32.u64 %0, t; }" : "=r"(a) : "l"(p));
    return a;
}
__device__ __forceinline__ void cp_async16(uint32_t saddr, const void* g) {
    asm volatile("cp.async.cg.shared.global [%0], [%1], 16;" :: "r"(saddr), "l"(g) : "memory");
}
#define CP_COMMIT() asm volatile("cp.async.commit_group;" ::: "memory")
template <int N> __device__ __forceinline__ void cp_wait_group() {
    asm volatile("cp.async.wait_group %0;" :: "n"(N) : "memory");
}
__device__ __forceinline__ void ldmx4(uint32_t* r, uint32_t addr) {
    asm volatile("ldmatrix.sync.aligned.m8n8.x4.shared.b16 {%0,%1,%2,%3}, [%4];"
                 : "=r"(r[0]), "=r"(r[1]), "=r"(r[2]), "=r"(r[3]) : "r"(addr));
}
__device__ __forceinline__ void mma16816(float* d, const uint32_t* a,
                                         uint32_t b0, uint32_t b1) {
    asm volatile("mma.sync.aligned.m16n8k16.row.col.f32.f16.f16.f32 "
                 "{%0,%1,%2,%3}, {%4,%5,%6,%7}, {%8,%9}, {%0,%1,%2,%3};"
                 : "+f"(d[0]), "+f"(d[1]), "+f"(d[2]), "+f"(d[3])
                 : "r"(a[0]), "r"(a[1]), "r"(a[2]), "r"(a[3]), "r"(b0), "r"(b1));
}

// ---------------------------------------------------------------------------
// GEMM: C = g_A (fp16, MxK) @ Bmat (fp16, NxK)^T. HalfOut: fp16 C (GEMM1) or
// f32 C (GEMM2). Fragment double-buffer: prefetch k16 i+1 during i's MMAs.
// Grid: x = m-block (128), y = n-block (8) -> co-launched CTAs share B slice.
// ---------------------------------------------------------------------------
template <bool HalfOut>
__global__ __launch_bounds__(GEMM_THREADS, 2)
void gemm_mma_kernel(const __half* __restrict__ Bmat,
                     void* __restrict__ Cout)
{
    extern __shared__ char smem_raw[];
    const uint32_t sbase = smem_u32(smem_raw);

    const int tid  = threadIdx.x;
    const int wid  = tid >> 5;
    const int lane = tid & 31;
    const int wm   = wid >> 2;          // 0..1 (m)
    const int wn   = wid & 3;           // 0..3 (n)
    const int bm0  = blockIdx.x * BM;   // raster: m fastest
    const int bn0  = blockIdx.y * BN;

    const char* gA = (const char*)g_A  + (size_t)bm0 * (K_DIM * 2);
    const char* gB = (const char*)Bmat + (size_t)bn0 * (K_DIM * 2);

    // cp.async mapping: 8 threads per 128B row, 32 rows per pass, 4 passes.
    const int lrow = tid >> 3;           // 0..31
    const int lcol = (tid & 7) * 16;     // 0..112

    auto load_stage = [&](int s, int kiter) {
        const uint32_t sa = sbase + s * STAGEB;
        const uint32_t sb = sa + TILEB;
        const size_t kb = (size_t)kiter * (BK * 2);
#pragma unroll
        for (int p = 0; p < 4; p++) {
            const int r = lrow + p * 32;
            const uint32_t sofs = r * ROWB + lcol;
            cp_async16(sa + sofs, gA + (size_t)r * (K_DIM * 2) + kb + lcol);
            cp_async16(sb + sofs, gB + (size_t)r * (K_DIM * 2) + kb + lcol);
        }
    };

    // ldmatrix per-thread base offsets
    const int l16 = lane & 15;
    const int lh  = lane >> 4;
    const uint32_t a_off = (uint32_t)((wm * 64 + l16) * ROWB + lh * 16);
    const uint32_t b_off = (uint32_t)((wn * 32 + l16) * ROWB + lh * 16);

    float acc[4][4][4];
#pragma unroll
    for (int mi = 0; mi < 4; mi++)
#pragma unroll
        for (int ni = 0; ni < 4; ni++)
#pragma unroll
            for (int q = 0; q < 4; q++) acc[mi][ni][q] = 0.f;

    // Double-buffered fragments
    uint32_t ar[2][4][4];
    uint32_t br[2][2][4];

    auto load_frags = [&](int buf, uint32_t sa, uint32_t sb, int ks) {
        const uint32_t kb = ks * 32;
#pragma unroll
        for (int mi = 0; mi < 4; mi++)
            ldmx4(ar[buf][mi], sa + a_off + mi * 16 * ROWB + kb);
        ldmx4(br[buf][0], sb + b_off + kb);
        ldmx4(br[buf][1], sb + b_off + 16 * ROWB + kb);
    };
    auto do_mma = [&](int buf) {
#pragma unroll
        for (int mi = 0; mi < 4; mi++) {
            mma16816(acc[mi][0], ar[buf][mi], br[buf][0][0], br[buf][0][2]);
            mma16816(acc[mi][1], ar[buf][mi], br[buf][0][1], br[buf][0][3]);
            mma16816(acc[mi][2], ar[buf][mi], br[buf][1][0], br[buf][1][2]);
            mma16816(acc[mi][3], ar[buf][mi], br[buf][1][1], br[buf][1][3]);
        }
    };

    // Prologue: fill NSTAGES-1 stages
#pragma unroll
    for (int s = 0; s < NSTAGES - 1; s++) { load_stage(s, s); CP_COMMIT(); }

    for (int j = 0; j < KITERS; j++) {
        cp_wait_group<NSTAGES - 2>();
        __syncthreads();

        const int s = j - (j / NSTAGES) * NSTAGES;      // j % 3
        const uint32_t sa = sbase + s * STAGEB;
        const uint32_t sb = sa + TILEB;

        // Prime buffer 0; cp.async for stage j+2 issued between prefetch and
        // MMAs so LSU work overlaps the tensor phase.
        load_frags(0, sa, sb, 0);

        const int jn = j + NSTAGES - 1;
        if (jn < KITERS) {
            load_stage(jn - (jn / NSTAGES) * NSTAGES, jn);
        }
        CP_COMMIT();

#pragma unroll
        for (int ks = 0; ks < 4; ks++) {
            if (ks < 3) load_frags((ks + 1) & 1, sa, sb, ks + 1);
            do_mma(ks & 1);
        }
    }

    // Epilogue: m16n8 d-frag: d0,d1 -> (lane/4, 2*(lane%4)); d2,d3 -> row+8
    const int r0 = lane >> 2;
    const int c0 = (lane & 3) * 2;
    const int mbase = bm0 + wm * 64;
    const int nbase = bn0 + wn * 32;
#pragma unroll
    for (int mi = 0; mi < 4; mi++) {
#pragma unroll
        for (int ni = 0; ni < 4; ni++) {
            const size_t rofs = (size_t)(mbase + mi * 16 + r0) * N_OUT + nbase + ni * 8 + c0;
            if (HalfOut) {
                __half* p = (__half*)Cout + rofs;
                *(__half2*)p = __halves2half2(__float2half_rn(acc[mi][ni][0]),
                                              __float2half_rn(acc[mi][ni][1]));
                *(__half2*)(p + 8 * N_OUT) = __halves2half2(__float2half_rn(acc[mi][ni][2]),
                                                            __float2half_rn(acc[mi][ni][3]));
            } else {
                float* p = (float*)Cout + rofs;
                *(float2*)p = make_float2(acc[mi][ni][0], acc[mi][ni][1]);
                *(float2*)(p + 8 * N_OUT) = make_float2(acc[mi][ni][2], acc[mi][ni][3]);
            }
        }
    }
}

// ---------------------------------------------------------------------------
// pack_A1: u (f32, 16384x1024) -> g_A (fp16, 16384x1024), float4 loads
// ---------------------------------------------------------------------------
__global__ __launch_bounds__(256)
void pack_A1_kernel(const float* __restrict__ u)
{
    const int idx = blockIdx.x * blockDim.x + threadIdx.x;   // M_ROWS*256 quads
    if (idx >= M_ROWS * 256) return;
    const float4 v = *(const float4*)(u + (size_t)idx * 4);
    __half2 h0 = __halves2half2(__float2half_rn(v.x), __float2half_rn(v.y));
    __half2 h1 = __halves2half2(__float2half_rn(v.z), __float2half_rn(v.w));
    ((__half2*)g_A)[2 * idx]     = h0;
    ((__half2*)g_A)[2 * idx + 1] = h1;
}

// ---------------------------------------------------------------------------
// pack_B (merged): z=0 -> g_B1 from [Br|Bi]; z=1 -> g_B2 from [Cr;-Ci].
// Output layout: B'[n][k] = fp16(W[k][n]), K-major.
// ---------------------------------------------------------------------------
__global__ __launch_bounds__(256)
void pack_B_kernel(const float* __restrict__ Br, const float* __restrict__ Bi,
                   const float* __restrict__ Cr, const float* __restrict__ Ci)
{
    __shared__ float tile[32][33];
    const int which = blockIdx.z;
    const int k0 = blockIdx.y * 32, n0 = blockIdx.x * 32;
    const int tx = threadIdx.x, ty = threadIdx.y;       // (32, 8)
#pragma unroll
    for (int j = 0; j < 32; j += 8) {
        const int k = k0 + ty + j, n = n0 + tx;
        float w;
        if (which == 0) {
            w = (n < N_DIM) ? Br[(size_t)k * N_DIM + n]
                            : Bi[(size_t)k * N_DIM + (n - N_DIM)];
        } else {
            w = (k < N_DIM) ? Cr[(size_t)k * N_OUT + n]
                            : -Ci[(size_t)(k - N_DIM) * N_OUT + n];
        }
        tile[ty + j][tx] = w;
    }
    __syncthreads();
    __half* dst = (which == 0) ? g_B1 : g_B2;
#pragma unroll
    for (int j = 0; j < 32; j += 8) {
        const int n = n0 + ty + j, k = k0 + tx;
        dst[(size_t)n * K_DIM + k] = __float2half_rn(tile[tx][ty + j]);
    }
}

// ---------------------------------------------------------------------------
// Elementwise + batch cumsum, fused with fp16 pack of x into g_A.
// Thread = (l-chunk of LCHUNK, np). Iterates l DOWNWARD within the chunk so
// e = len-l-1 increases by 1 per step: Lambda^(e+1) = Lambda^e * (lam_mod *
// e^{i*arg}). mag multiplies by lam_mod < 1 (stable). Anchor sincosf+__expf
// fires once per (b,n) per chunk, at dl==LCHUNK-1 (chunk top) or at the e==1
// crossing; both predicates are warp-uniform (block spans np for a single l).
// ---------------------------------------------------------------------------
__global__ __launch_bounds__(256)
void lru_elem_pack_kernel(const int* __restrict__ lengths,
                          const float* __restrict__ nu_log,
                          const float* __restrict__ theta_log)
{
    const int np = threadIdx.x;          // 0..255 (n-pair)
    const int l0 = blockIdx.x * LCHUNK;  // chunk base
    const int n  = 2 * np;

    float lamlog[2], argv[2], Sr[2], Si[2];
#pragma unroll
    for (int c = 0; c < 2; c++) {
        const float lam_mod = expf(-expf(__ldg(&nu_log[n + c])));
        lamlog[c] = logf(lam_mod);
        argv[c]   = expf(__ldg(&theta_log[n + c]));
        float ss, cc;
        sincosf(argv[c], &ss, &cc);
        Sr[c] = lam_mod * cc;            // step rotation: lam_mod * e^{i*arg}
        Si[c] = lam_mod * ss;
    }

    int len[B_SZ];
#pragma unroll
    for (int b = 0; b < B_SZ; b++) len[b] = __ldg(&lengths[b]);

    float Lr[2][B_SZ], Li[2][B_SZ];      // recurrence state per (c, b)

#pragma unroll
    for (int dl = LCHUNK - 1; dl >= 0; dl--) {
        const int l = l0 + dl;
        float xr0 = 0.f, xi0 = 0.f, xr1 = 0.f, xi1 = 0.f;
#pragma unroll
        for (int b = 0; b < B_SZ; b++) {
            const __half2* sr = (const __half2*)(g_Bu + ((size_t)(b * L_SEQ + l)) * N_OUT);
            const float2 vr = __half22float2(sr[np]);
            const float2 vi = __half22float2(sr[256 + np]);

            const int e = len[b] - (l + 1);
            if (e > 0) {                             // warp-uniform
                if (dl == LCHUNK - 1 || e == 1) {    // anchor: full evaluation
                    const float fe = (float)e;
#pragma unroll
                    for (int c = 0; c < 2; c++) {
                        const float mag = __expf(fe * lamlog[c]);
                        float s, co;
                        sincosf(fe * argv[c], &s, &co);
                        Lr[c][b] = mag * co;
                        Li[c][b] = mag * s;
                    }
                } else {                             // step: Lambda *= S
#pragma unroll
                    for (int c = 0; c < 2; c++) {
                        const float t = Lr[c][b] * Sr[c] - Li[c][b] * Si[c];
                        Li[c][b] = Lr[c][b] * Si[c] + Li[c][b] * Sr[c];
                        Lr[c][b] = t;
                    }
                }
                xr0 += Lr[0][b] * vr.x - Li[0][b] * vi.x;
                xi0 += Lr[0][b] * vi.x + Li[0][b] * vr.x;
                xr1 += Lr[1][b] * vr.y - Li[1][b] * vi.y;
                xi1 += Lr[1][b] * vi.y + Li[1][b] * vr.y;
            } else {                                 // e == 0: Lambda^0 = 1
                xr0 += vr.x;  xi0 += vi.x;
                xr1 += vr.y;  xi1 += vi.y;
            }

            __half2* row = (__half2*)(g_A + ((size_t)(b * L_SEQ + l)) * K_DIM);
            row[np]       = __halves2half2(__float2half_rn(xr0), __float2half_rn(xr1));
            row[256 + np] = __halves2half2(__float2half_rn(xi0), __float2half_rn(xi1));
        }
    }
}

// ---------------------------------------------------------------------------
// Launch. Inputs: 0:u 1:lenghts 2:nu_log 3:theta_log 4:Br 5:Bi 6:Cr 7:Ci
// Output: y (B,L,H) f32
// ---------------------------------------------------------------------------
extern "C" void kernel_launch(void* const* d_in, const int* in_sizes, int n_in,
                              void* d_out, int out_size)
{
    const float* u         = (const float*)d_in[0];
    const int*   lengths   = (const int*)d_in[1];
    const float* nu_log    = (const float*)d_in[2];
    const float* theta_log = (const float*)d_in[3];
    const float* Br        = (const float*)d_in[4];
    const float* Bi        = (const float*)d_in[5];
    const float* Cr        = (const float*)d_in[6];
    const float* Ci        = (const float*)d_in[7];
    float* y = (float*)d_out;

    cudaFuncSetAttribute(gemm_mma_kernel<true>,
                         cudaFuncAttributeMaxDynamicSharedMemorySize, SMEM_DYN);
    cudaFuncSetAttribute(gemm_mma_kernel<false>,
                         cudaFuncAttributeMaxDynamicSharedMemorySize, SMEM_DYN);

    void *pB1 = nullptr, *pB2 = nullptr, *pBu = nullptr;
    cudaGetSymbolAddress(&pB1, g_B1);
    cudaGetSymbolAddress(&pB2, g_B2);
    cudaGetSymbolAddress(&pBu, g_Bu);

    // 1. Pack A (float4) and both weight matrices (merged kernel)
    pack_A1_kernel<<<(M_ROWS * 256) / 256, 256>>>(u);
    dim3 pb(32, 8), pg(32, 32, 2);
    pack_B_kernel<<<pg, pb>>>(Br, Bi, Cr, Ci);

    // 2. GEMM1: Bu = A @ B1^T  -> g_Bu (fp16)
    dim3 gg(M_ROWS / BM, N_OUT / BN);   // (128, 8): m fastest
    gemm_mma_kernel<true><<<gg, GEMM_THREADS, SMEM_DYN>>>(
        (const __half*)pB1, pBu);

    // 3. Elementwise Lambda^e * Bu + batch cumsum (l-chunk recurrence),
    //    packed back into g_A
    lru_elem_pack_kernel<<<L_SEQ / LCHUNK, 256>>>(lengths, nu_log, theta_log);

    // 4. GEMM2: y = A @ B2^T  -> f32 output
    gemm_mma_kernel<false><<<gg, GEMM_THREADS, SMEM_DYN>>>(
        (const __half*)pB2, (void*)y);
}

// round 17
// speedup vs baseline: 1.6073x; 1.6073x over previous
#include <cuda_runtime.h>
#include <cuda_fp16.h>
#include <math.h>
#include <stdint.h>

// ---------------------------------------------------------------------------
// Problem constants
// ---------------------------------------------------------------------------
#define B_SZ   8
#define L_SEQ  2048
#define H_DIM  1024
#define N_DIM  512
#define M_ROWS 16384            // B*L
#define K_DIM  1024             // pure fp16: K = 1024 for both GEMMs
#define N_OUT  1024

// GEMM config (converged optimum): 128x128 CTA tile, 8 warps (2m x 4n) of
// 64x32, BK=64, 3 stages, 2 CTAs/SM, register double-buffered fragments.
#define BM 128
#define BN 128
#define BK 64                   // fp16 elems per stage row (128 B data)
#define NSTAGES 3
#define KITERS (K_DIM / BK)     // 16
#define GEMM_THREADS 256

// Padded rows: 64 fp16 = 128B data + 16B pad = 144B -> conflict-free ldmatrix.
#define ROWB 144
#define TILEB (128 * ROWB)      // 18432 B per operand tile
#define STAGEB (2 * TILEB)      // 36864 B per stage
#define SMEM_DYN (NSTAGES * STAGEB)   // 110592 B -> 2 CTAs/SM

// ---------------------------------------------------------------------------
// Static device buffers (allocation-free scratch)
// ---------------------------------------------------------------------------
__device__ __half g_A[(size_t)M_ROWS * K_DIM];              // 32 MB
__device__ __half g_B1[(size_t)N_OUT * K_DIM];              // 2 MB
__device__ __half g_B2[(size_t)N_OUT * K_DIM];              // 2 MB
__device__ __half g_Bu[(size_t)M_ROWS * N_OUT];             // 32 MB (Bu fp16)

// ---------------------------------------------------------------------------
// PTX helpers (sm_80-class only — legal on base compute_103 target)
// ---------------------------------------------------------------------------
__device__ __forceinline__ uint32_t smem_u32(const void* p) {
    uint32_t a;
    asm("{ .reg .u64 t; cvta.to.shared.u64 t, %1; cvt.u32.u64 %0, t; }" : "=r"(a) : "l"(p));
    return a;
}
__device__ __forceinline__ void cp_async16(uint32_t saddr, const void* g) {
    asm volatile("cp.async.cg.shared.global [%0], [%1], 16;" :: "r"(saddr), "l"(g) : "memory");
}
#define CP_COMMIT() asm volatile("cp.async.commit_group;" ::: "memory")
template <int N> __device__ __forceinline__ void cp_wait_group() {
    asm volatile("cp.async.wait_group %0;" :: "n"(N) : "memory");
}
__device__ __forceinline__ void ldmx4(uint32_t* r, uint32_t addr) {
    asm volatile("ldmatrix.sync.aligned.m8n8.x4.shared.b16 {%0,%1,%2,%3}, [%4];"
                 : "=r"(r[0]), "=r"(r[1]), "=r"(r[2]), "=r"(r[3]) : "r"(addr));
}
__device__ __forceinline__ void mma16816(float* d, const uint32_t* a,
                                         uint32_t b0, uint32_t b1) {
    asm volatile("mma.sync.aligned.m16n8k16.row.col.f32.f16.f16.f32 "
                 "{%0,%1,%2,%3}, {%4,%5,%6,%7}, {%8,%9}, {%0,%1,%2,%3};"
                 : "+f"(d[0]), "+f"(d[1]), "+f"(d[2]), "+f"(d[3])
                 : "r"(a[0]), "r"(a[1]), "r"(a[2]), "r"(a[3]), "r"(b0), "r"(b1));
}

// ---------------------------------------------------------------------------
// GEMM: C = g_A (fp16, MxK) @ Bmat (fp16, NxK)^T. HalfOut: fp16 C (GEMM1) or
// f32 C (GEMM2). Fragment double-buffer: prefetch k16 i+1 during i's MMAs.
// Grid: x = m-block (128), y = n-block (8) -> co-launched CTAs share B slice.
// ---------------------------------------------------------------------------
template <bool HalfOut>
__global__ __launch_bounds__(GEMM_THREADS, 2)
void gemm_mma_kernel(const __half* __restrict__ Bmat,
                     void* __restrict__ Cout)
{
    extern __shared__ char smem_raw[];
    const uint32_t sbase = smem_u32(smem_raw);

    const int tid  = threadIdx.x;
    const int wid  = tid >> 5;
    const int lane = tid & 31;
    const int wm   = wid >> 2;          // 0..1 (m)
    const int wn   = wid & 3;           // 0..3 (n)
    const int bm0  = blockIdx.x * BM;   // raster: m fastest
    const int bn0  = blockIdx.y * BN;

    const char* gA = (const char*)g_A  + (size_t)bm0 * (K_DIM * 2);
    const char* gB = (const char*)Bmat + (size_t)bn0 * (K_DIM * 2);

    // cp.async mapping: 8 threads per 128B row, 32 rows per pass, 4 passes.
    const int lrow = tid >> 3;           // 0..31
    const int lcol = (tid & 7) * 16;     // 0..112

    auto load_stage = [&](int s, int kiter) {
        const uint32_t sa = sbase + s * STAGEB;
        const uint32_t sb = sa + TILEB;
        const size_t kb = (size_t)kiter * (BK * 2);
#pragma unroll
        for (int p = 0; p < 4; p++) {
            const int r = lrow + p * 32;
            const uint32_t sofs = r * ROWB + lcol;
            cp_async16(sa + sofs, gA + (size_t)r * (K_DIM * 2) + kb + lcol);
            cp_async16(sb + sofs, gB + (size_t)r * (K_DIM * 2) + kb + lcol);
        }
    };

    // ldmatrix per-thread base offsets
    const int l16 = lane & 15;
    const int lh  = lane >> 4;
    const uint32_t a_off = (uint32_t)((wm * 64 + l16) * ROWB + lh * 16);
    const uint32_t b_off = (uint32_t)((wn * 32 + l16) * ROWB + lh * 16);

    float acc[4][4][4];
#pragma unroll
    for (int mi = 0; mi < 4; mi++)
#pragma unroll
        for (int ni = 0; ni < 4; ni++)
#pragma unroll
            for (int q = 0; q < 4; q++) acc[mi][ni][q] = 0.f;

    // Double-buffered fragments
    uint32_t ar[2][4][4];
    uint32_t br[2][2][4];

    auto load_frags = [&](int buf, uint32_t sa, uint32_t sb, int ks) {
        const uint32_t kb = ks * 32;
#pragma unroll
        for (int mi = 0; mi < 4; mi++)
            ldmx4(ar[buf][mi], sa + a_off + mi * 16 * ROWB + kb);
        ldmx4(br[buf][0], sb + b_off + kb);
        ldmx4(br[buf][1], sb + b_off + 16 * ROWB + kb);
    };
    auto do_mma = [&](int buf) {
#pragma unroll
        for (int mi = 0; mi < 4; mi++) {
            mma16816(acc[mi][0], ar[buf][mi], br[buf][0][0], br[buf][0][2]);
            mma16816(acc[mi][1], ar[buf][mi], br[buf][0][1], br[buf][0][3]);
            mma16816(acc[mi][2], ar[buf][mi], br[buf][1][0], br[buf][1][2]);
            mma16816(acc[mi][3], ar[buf][mi], br[buf][1][1], br[buf][1][3]);
        }
    };

    // Prologue: fill NSTAGES-1 stages
#pragma unroll
    for (int s = 0; s < NSTAGES - 1; s++) { load_stage(s, s); CP_COMMIT(); }

    for (int j = 0; j < KITERS; j++) {
        cp_wait_group<NSTAGES - 2>();
        __syncthreads();

        const int s = j - (j / NSTAGES) * NSTAGES;      // j % 3
        const uint32_t sa = sbase + s * STAGEB;
        const uint32_t sb = sa + TILEB;

        // Prime buffer 0; cp.async for stage j+2 issued between prefetch and
        // MMAs so LSU work overlaps the tensor phase.
        load_frags(0, sa, sb, 0);

        const int jn = j + NSTAGES - 1;
        if (jn < KITERS) {
            load_stage(jn - (jn / NSTAGES) * NSTAGES, jn);
        }
        CP_COMMIT();

#pragma unroll
        for (int ks = 0; ks < 4; ks++) {
            if (ks < 3) load_frags((ks + 1) & 1, sa, sb, ks + 1);
            do_mma(ks & 1);
        }
    }

    // Epilogue: m16n8 d-frag: d0,d1 -> (lane/4, 2*(lane%4)); d2,d3 -> row+8
    const int r0 = lane >> 2;
    const int c0 = (lane & 3) * 2;
    const int mbase = bm0 + wm * 64;
    const int nbase = bn0 + wn * 32;
#pragma unroll
    for (int mi = 0; mi < 4; mi++) {
#pragma unroll
        for (int ni = 0; ni < 4; ni++) {
            const size_t rofs = (size_t)(mbase + mi * 16 + r0) * N_OUT + nbase + ni * 8 + c0;
            if (HalfOut) {
                __half* p = (__half*)Cout + rofs;
                *(__half2*)p = __halves2half2(__float2half_rn(acc[mi][ni][0]),
                                              __float2half_rn(acc[mi][ni][1]));
                *(__half2*)(p + 8 * N_OUT) = __halves2half2(__float2half_rn(acc[mi][ni][2]),
                                                            __float2half_rn(acc[mi][ni][3]));
            } else {
                float* p = (float*)Cout + rofs;
                *(float2*)p = make_float2(acc[mi][ni][0], acc[mi][ni][1]);
                *(float2*)(p + 8 * N_OUT) = make_float2(acc[mi][ni][2], acc[mi][ni][3]);
            }
        }
    }
}

// ---------------------------------------------------------------------------
// pack_A1: u (f32, 16384x1024) -> g_A (fp16, 16384x1024), float4 loads
// ---------------------------------------------------------------------------
__global__ __launch_bounds__(256)
void pack_A1_kernel(const float* __restrict__ u)
{
    const int idx = blockIdx.x * blockDim.x + threadIdx.x;   // M_ROWS*256 quads
    if (idx >= M_ROWS * 256) return;
    const float4 v = *(const float4*)(u + (size_t)idx * 4);
    __half2 h0 = __halves2half2(__float2half_rn(v.x), __float2half_rn(v.y));
    __half2 h1 = __halves2half2(__float2half_rn(v.z), __float2half_rn(v.w));
    ((__half2*)g_A)[2 * idx]     = h0;
    ((__half2*)g_A)[2 * idx + 1] = h1;
}

// ---------------------------------------------------------------------------
// pack_B (merged): z=0 -> g_B1 from [Br|Bi]; z=1 -> g_B2 from [Cr;-Ci].
// Output layout: B'[n][k] = fp16(W[k][n]), K-major.
// ---------------------------------------------------------------------------
__global__ __launch_bounds__(256)
void pack_B_kernel(const float* __restrict__ Br, const float* __restrict__ Bi,
                   const float* __restrict__ Cr, const float* __restrict__ Ci)
{
    __shared__ float tile[32][33];
    const int which = blockIdx.z;
    const int k0 = blockIdx.y * 32, n0 = blockIdx.x * 32;
    const int tx = threadIdx.x, ty = threadIdx.y;       // (32, 8)
#pragma unroll
    for (int j = 0; j < 32; j += 8) {
        const int k = k0 + ty + j, n = n0 + tx;
        float w;
        if (which == 0) {
            w = (n < N_DIM) ? Br[(size_t)k * N_DIM + n]
                            : Bi[(size_t)k * N_DIM + (n - N_DIM)];
        } else {
            w = (k < N_DIM) ? Cr[(size_t)k * N_OUT + n]
                            : -Ci[(size_t)(k - N_DIM) * N_OUT + n];
        }
        tile[ty + j][tx] = w;
    }
    __syncthreads();
    __half* dst = (which == 0) ? g_B1 : g_B2;
#pragma unroll
    for (int j = 0; j < 32; j += 8) {
        const int n = n0 + ty + j, k = k0 + tx;
        dst[(size_t)n * K_DIM + k] = __float2half_rn(tile[tx][ty + j]);
    }
}

// ---------------------------------------------------------------------------
// Elementwise + batch cumsum, fused with fp16 pack of x into g_A.
// g_Bu row r=b*L+l (fp16): cols [0,512)=Bu_r, [512,1024)=Bu_i.
// g_A row r: k=[0,512)=fp16(xr), [512,1024)=fp16(xi).
// e = max(len_b - l - 1, 0): when clamped to 0, Lambda^e == 1 exactly, so the
// complex product degenerates to Bu itself — skip exp/sincos entirely. The
// predicate depends only on (b, l) and each warp spans a single l (np is the
// fast index), so the branch is warp-uniform (no divergence). Expected ~50%
// of (b, l) pairs clamp (lengths ~ U[0, L)).
// ---------------------------------------------------------------------------
__global__ __launch_bounds__(256)
void lru_elem_pack_kernel(const int* __restrict__ lengths,
                          const float* __restrict__ nu_log,
                          const float* __restrict__ theta_log)
{
    const int idx = blockIdx.x * blockDim.x + threadIdx.x;   // L_SEQ * 256 pairs
    if (idx >= L_SEQ * 256) return;
    const int l  = idx >> 8;
    const int np = idx & 255;
    const int n  = 2 * np;

    float lamlog[2], argv[2];
#pragma unroll
    for (int c = 0; c < 2; c++) {
        const float lam_mod = expf(-expf(__ldg(&nu_log[n + c])));
        lamlog[c] = logf(lam_mod);
        argv[c]   = expf(__ldg(&theta_log[n + c]));
    }

    float2 vr[B_SZ], vi[B_SZ];
#pragma unroll
    for (int b = 0; b < B_SZ; b++) {
        const __half2* sr = (const __half2*)(g_Bu + ((size_t)(b * L_SEQ + l)) * N_OUT);
        vr[b] = __half22float2(sr[np]);
        vi[b] = __half22float2(sr[256 + np]);
    }

    float xr0 = 0.f, xr1 = 0.f, xi0 = 0.f, xi1 = 0.f;
#pragma unroll
    for (int b = 0; b < B_SZ; b++) {
        const int len = __ldg(&lengths[b]);
        if (len > l + 1) {                       // e > 0 (warp-uniform branch)
            const float e = (float)(len - (l + 1));
            float mag, s, c_;
            mag = __expf(e * lamlog[0]); sincosf(e * argv[0], &s, &c_);
            float Lr = mag * c_, Li = mag * s;
            xr0 += Lr * vr[b].x - Li * vi[b].x;
            xi0 += Lr * vi[b].x + Li * vr[b].x;
            mag = __expf(e * lamlog[1]); sincosf(e * argv[1], &s, &c_);
            Lr = mag * c_; Li = mag * s;
            xr1 += Lr * vr[b].y - Li * vi[b].y;
            xi1 += Lr * vi[b].y + Li * vr[b].y;
        } else {                                 // e == 0: Lambda^0 = 1
            xr0 += vr[b].x;  xi0 += vi[b].x;
            xr1 += vr[b].y;  xi1 += vi[b].y;
        }

        __half2* row = (__half2*)(g_A + ((size_t)(b * L_SEQ + l)) * K_DIM);
        row[np]       = __halves2half2(__float2half_rn(xr0), __float2half_rn(xr1)); // k=n
        row[256 + np] = __halves2half2(__float2half_rn(xi0), __float2half_rn(xi1)); // k=512+n
    }
}

// ---------------------------------------------------------------------------
// Launch. Inputs: 0:u 1:lenghts 2:nu_log 3:theta_log 4:Br 5:Bi 6:Cr 7:Ci
// Output: y (B,L,H) f32
// ---------------------------------------------------------------------------
extern "C" void kernel_launch(void* const* d_in, const int* in_sizes, int n_in,
                              void* d_out, int out_size)
{
    const float* u         = (const float*)d_in[0];
    const int*   lengths   = (const int*)d_in[1];
    const float* nu_log    = (const float*)d_in[2];
    const float* theta_log = (const float*)d_in[3];
    const float* Br        = (const float*)d_in[4];
    const float* Bi        = (const float*)d_in[5];
    const float* Cr        = (const float*)d_in[6];
    const float* Ci        = (const float*)d_in[7];
    float* y = (float*)d_out;

    cudaFuncSetAttribute(gemm_mma_kernel<true>,
                         cudaFuncAttributeMaxDynamicSharedMemorySize, SMEM_DYN);
    cudaFuncSetAttribute(gemm_mma_kernel<false>,
                         cudaFuncAttributeMaxDynamicSharedMemorySize, SMEM_DYN);

    void *pB1 = nullptr, *pB2 = nullptr, *pBu = nullptr;
    cudaGetSymbolAddress(&pB1, g_B1);
    cudaGetSymbolAddress(&pB2, g_B2);
    cudaGetSymbolAddress(&pBu, g_Bu);

    // 1. Pack A (float4) and both weight matrices (merged kernel)
    pack_A1_kernel<<<(M_ROWS * 256) / 256, 256>>>(u);
    dim3 pb(32, 8), pg(32, 32, 2);
    pack_B_kernel<<<pg, pb>>>(Br, Bi, Cr, Ci);

    // 2. GEMM1: Bu = A @ B1^T  -> g_Bu (fp16)
    dim3 gg(M_ROWS / BM, N_OUT / BN);   // (128, 8): m fastest
    gemm_mma_kernel<true><<<gg, GEMM_THREADS, SMEM_DYN>>>(
        (const __half*)pB1, pBu);

    // 3. Elementwise Lambda^e * Bu + batch cumsum, packed back into g_A
    lru_elem_pack_kernel<<<(L_SEQ * 256) / 256, 256>>>(lengths, nu_log, theta_log);

    // 4. GEMM2: y = A @ B2^T  -> f32 output
    gemm_mma_kernel<false><<<gg, GEMM_THREADS, SMEM_DYN>>>(
        (const __half*)pB2, (void*)y);
}